// round 14
// baseline (speedup 1.0000x reference)
#include <cuda_runtime.h>
#include <cuda_fp16.h>
#include <math.h>
#include <stdint.h>

#define D_MODEL 1024
#define D_FF    4096
#define BATCH   8
#define SEQ     2048
#define M_TOT   (BATCH * SEQ)   // 16384
#define WSLOT   ((size_t)D_MODEL * D_FF)

// ---------------- scratch (allocation-free: __device__ globals) ----------------
__device__ __half g_Xh [(size_t)M_TOT * D_MODEL];  // 32 MB
__device__ __half g_H  [(size_t)M_TOT * D_FF];     // 128 MB expert H
__device__ __half g_H2 [(size_t)M_TOT * D_FF];     // 128 MB shared H
__device__ __half g_Wa [6 * WSLOT];                // Wi0[0:5], sWi0[5]
__device__ __half g_Wb [6 * WSLOT];                // Wi1[0:5], sWi1[5]
__device__ __half g_Wc [6 * WSLOT];                // Wo [0:5], sWo [5]
__device__ float  g_gp [8 * BATCH * 2 * D_MODEL];  // row0 partials (k-split 8)
__device__ float  g_hp [32 * BATCH * D_MODEL];     // gate1 partials (k-split 32)
__device__ float  g_W  [BATCH * 2];                // gate weights

// ---------------- helpers ------------------------------------------------------
__device__ __forceinline__ uint32_t smem_u32(const void* p) {
    uint32_t a;
    asm("{ .reg .u64 t; cvta.to.shared.u64 t, %1; cvt.u32.u64 %0, t; }"
        : "=r"(a) : "l"(p));
    return a;
}
__device__ __forceinline__ float gelu_tanh(float x) {
    float x3 = x * x * x;
    return 0.5f * x * (1.f + tanhf(0.7978845608028654f * (x + 0.044715f * x3)));
}
__device__ __forceinline__ void cp_async16(uint32_t saddr, const void* gaddr) {
    asm volatile("cp.async.cg.shared.global [%0], [%1], 16;"
                 :: "r"(saddr), "l"(gaddr) : "memory");
}
#define CP_COMMIT() asm volatile("cp.async.commit_group;" ::: "memory")
#define CP_WAIT1()  asm volatile("cp.async.wait_group 1;" ::: "memory")

__device__ __forceinline__ void ldsm4(uint32_t* r, uint32_t addr) {
    asm volatile("ldmatrix.sync.aligned.m8n8.x4.shared.b16 {%0,%1,%2,%3}, [%4];"
                 : "=r"(r[0]), "=r"(r[1]), "=r"(r[2]), "=r"(r[3]) : "r"(addr));
}
__device__ __forceinline__ void ldsm4t(uint32_t* r, uint32_t addr) {
    asm volatile("ldmatrix.sync.aligned.m8n8.x4.trans.shared.b16 {%0,%1,%2,%3}, [%4];"
                 : "=r"(r[0]), "=r"(r[1]), "=r"(r[2]), "=r"(r[3]) : "r"(addr));
}
__device__ __forceinline__ void mma16816(float* d, const uint32_t* a, const uint32_t* b) {
    asm volatile(
        "mma.sync.aligned.m16n8k16.row.col.f32.f16.f16.f32 "
        "{%0,%1,%2,%3}, {%4,%5,%6,%7}, {%8,%9}, {%0,%1,%2,%3};"
        : "+f"(d[0]), "+f"(d[1]), "+f"(d[2]), "+f"(d[3])
        : "r"(a[0]), "r"(a[1]), "r"(a[2]), "r"(a[3]), "r"(b[0]), "r"(b[1]));
}
__device__ __forceinline__ void red_add_f32(float* addr, float v) {
    asm volatile("red.global.add.f32 [%0], %1;" :: "l"(addr), "f"(v) : "memory");
}

// ================================================================================
// Fused dual up-projection (proven): H = half(gelu(X@B0) * (X@B1)).
// ================================================================================
#define UP_STAGE 32768
#define UP_SMEM  (3 * UP_STAGE)

__device__ __forceinline__ void up_fill(uint32_t st, const __half* __restrict__ A,
                                        const __half* __restrict__ B0,
                                        const __half* __restrict__ B1,
                                        int rowBase, int colBase, int k0, int tid)
{
#pragma unroll
    for (int i = 0; i < 4; i++) {
        int c = tid + i * 256;
        int row = c >> 3, kc = c & 7;
        uint32_t dst = st + (row << 7) + (((kc ^ row) & 7) << 4);
        cp_async16(dst, A + (size_t)(rowBase + row) * D_MODEL + k0 + (kc << 3));
    }
#pragma unroll
    for (int i = 0; i < 2; i++) {
        int c = tid + i * 256;
        int row = c >> 3, nc = c & 7;
        uint32_t dst = st + 16384 + (row << 7) + (((nc ^ row) & 7) << 4);
        cp_async16(dst, B0 + (size_t)(k0 + row) * D_FF + colBase + (nc << 3));
    }
#pragma unroll
    for (int i = 0; i < 2; i++) {
        int c = tid + i * 256;
        int row = c >> 3, nc = c & 7;
        uint32_t dst = st + 24576 + (row << 7) + (((nc ^ row) & 7) << 4);
        cp_async16(dst, B1 + (size_t)(k0 + row) * D_FF + colBase + (nc << 3));
    }
}

__global__ __launch_bounds__(256, 2)
void up_fused(const __half* __restrict__ A, const __half* __restrict__ Wa,
              const __half* __restrict__ Wb, __half* __restrict__ He,
              __half* __restrict__ Hs, const int* __restrict__ labels)
{
    extern __shared__ char smem[];
    const uint32_t sb = smem_u32(smem);
    const int tid = threadIdx.x, lane = tid & 31, warp = tid >> 5;
    const int rowBase = blockIdx.y * 128, colBase = blockIdx.x * 64;
    const int slot = blockIdx.z ? 5 : labels[rowBase / SEQ];
    __half* H = blockIdx.z ? Hs : He;
    const __half* B0 = Wa + (size_t)slot * WSLOT;
    const __half* B1 = Wb + (size_t)slot * WSLOT;

    const int wm = (warp >> 1) * 32, wn = (warp & 1) * 32;
    const int lr = lane >> 2, lc = lane & 3;
    const int hi = lane >> 4;

    float acc[2][2][4][4];
#pragma unroll
    for (int m = 0; m < 2; m++)
#pragma unroll
        for (int mt = 0; mt < 2; mt++)
#pragma unroll
            for (int nt = 0; nt < 4; nt++)
#pragma unroll
                for (int i = 0; i < 4; i++) acc[m][mt][nt][i] = 0.f;

    const int aRow = wm + (lane & 15);
    const uint32_t aOff = (uint32_t)aRow << 7;
    const uint32_t a_r7 = aRow & 7;
    const uint32_t bRowOff = (uint32_t)(lane & 15) << 7;
    const uint32_t b_r7 = lane & 7;
    uint32_t ncSw[2];
#pragma unroll
    for (int p = 0; p < 2; p++) {
        int nchunk = (wn >> 3) + p * 2 + hi;
        ncSw[p] = (uint32_t)((nchunk ^ b_r7) & 7) << 4;
    }

    const int T = D_MODEL / 64;
    up_fill(sb, A, B0, B1, rowBase, colBase, 0, tid);             CP_COMMIT();
    up_fill(sb + UP_STAGE, A, B0, B1, rowBase, colBase, 64, tid); CP_COMMIT();

    int buf = 0;
    for (int t = 0; t < T; t++) {
        CP_WAIT1();
        __syncthreads();
        const uint32_t base  = sb + (uint32_t)buf * UP_STAGE;
        const uint32_t aBase = base + aOff;

        const int tn = t + 2;
        if (tn < T) {
            int nb = buf + 2; if (nb >= 3) nb -= 3;
            up_fill(sb + (uint32_t)nb * UP_STAGE, A, B0, B1,
                    rowBase, colBase, tn * 64, tid);
        }
        CP_COMMIT();

#pragma unroll
        for (int ks = 0; ks < 4; ks++) {
            uint32_t a[2][4], b[2][2][4];
            const uint32_t csw = (uint32_t)(((ks * 2 + hi) ^ (int)a_r7) << 4);
            ldsm4(a[0], aBase + csw);
            ldsm4(a[1], aBase + (16u << 7) + csw);
            const uint32_t bk = base + 16384 + bRowOff + (uint32_t)ks * 2048;
#pragma unroll
            for (int m = 0; m < 2; m++)
#pragma unroll
                for (int p = 0; p < 2; p++)
                    ldsm4t(b[m][p], bk + (uint32_t)m * 8192 + ncSw[p]);
#pragma unroll
            for (int m = 0; m < 2; m++)
#pragma unroll
                for (int mt = 0; mt < 2; mt++)
#pragma unroll
                    for (int nt = 0; nt < 4; nt++)
                        mma16816(acc[m][mt][nt], a[mt],
                                 &b[m][nt >> 1][(nt & 1) * 2]);
        }
        buf++; if (buf == 3) buf = 0;
    }

#pragma unroll
    for (int mt = 0; mt < 2; mt++) {
        const int r0 = rowBase + wm + mt * 16 + lr;
#pragma unroll
        for (int nt = 0; nt < 4; nt++) {
            const int c = colBase + wn + nt * 8 + lc * 2;
            const size_t i0 = (size_t)r0 * D_FF + c;
            const size_t i1 = i0 + (size_t)8 * D_FF;
            float v0 = gelu_tanh(acc[0][mt][nt][0]) * acc[1][mt][nt][0];
            float v1 = gelu_tanh(acc[0][mt][nt][1]) * acc[1][mt][nt][1];
            float v2 = gelu_tanh(acc[0][mt][nt][2]) * acc[1][mt][nt][2];
            float v3 = gelu_tanh(acc[0][mt][nt][3]) * acc[1][mt][nt][3];
            *(__half2*)(H + i0) = __floats2half2_rn(v0, v1);
            *(__half2*)(H + i1) = __floats2half2_rn(v2, v3);
        }
    }
}

// ================================================================================
// Down GEMM, phase-split over grid-z; weighted atomic accumulation into out.
// out zeroed by cvt_all; each element gets exactly 2 adds (commutative -> det.).
// ================================================================================
#define DN_ABYTES 16384
#define DN_STAGE  32768
#define DN_SMEM   (3 * DN_STAGE)

__device__ __forceinline__ void dn_fill(uint32_t st, const __half* __restrict__ A,
                                        const __half* __restrict__ Bp,
                                        int rowBase, int colBase, int k0, int tid)
{
#pragma unroll
    for (int i = 0; i < 4; i++) {
        int c = tid + i * 256;
        int row = c >> 3, kc = c & 7;
        uint32_t dst = st + (row << 7) + (((kc ^ row) & 7) << 4);
        cp_async16(dst, A + (size_t)(rowBase + row) * D_FF + k0 + (kc << 3));
    }
#pragma unroll
    for (int i = 0; i < 4; i++) {
        int c = tid + i * 256;
        int row = c >> 4, nc = c & 15;
        uint32_t dst = st + DN_ABYTES + (row << 8) +
                       ((((nc ^ row) & 7) | (nc & 8)) << 4);
        cp_async16(dst, Bp + (size_t)(k0 + row) * D_MODEL + colBase + (nc << 3));
    }
}

__global__ __launch_bounds__(256, 2)
void dn_split(const __half* __restrict__ He, const __half* __restrict__ Hs,
              const __half* __restrict__ Wc, float* __restrict__ out,
              const int* __restrict__ labels, const float* __restrict__ w)
{
    extern __shared__ char smem[];
    const uint32_t sb = smem_u32(smem);
    const int tid = threadIdx.x, lane = tid & 31, warp = tid >> 5;
    const int rowBase = blockIdx.y * 128, colBase = blockIdx.x * 128;
    const int batch = rowBase / SEQ;
    const int ph = blockIdx.z;

    const __half* A  = ph ? Hs : He;
    const __half* Bp = Wc + (size_t)(ph ? 5 : labels[batch]) * WSLOT;

    const int wm = (warp >> 1) * 32, wn = (warp & 1) * 64;
    const int lr = lane >> 2, lc = lane & 3;
    const int hi = lane >> 4;

    float acc[2][8][4];
#pragma unroll
    for (int mt = 0; mt < 2; mt++)
#pragma unroll
        for (int nt = 0; nt < 8; nt++)
#pragma unroll
            for (int i = 0; i < 4; i++) acc[mt][nt][i] = 0.f;

    const int aRow = wm + (lane & 15);
    const uint32_t aOff = (uint32_t)aRow << 7;
    const uint32_t a_r7 = aRow & 7;
    const uint32_t bRowOff = (uint32_t)(lane & 15) << 8;
    const uint32_t b_r7 = lane & 7;
    uint32_t ncSw[4];
#pragma unroll
    for (int p = 0; p < 4; p++) {
        int nchunk = (wn >> 3) + p * 2 + hi;
        ncSw[p] = (uint32_t)((nchunk & 8) | ((nchunk ^ b_r7) & 7)) << 4;
    }

    const int T = D_FF / 64;   // 64 stages
    dn_fill(sb, A, Bp, rowBase, colBase, 0, tid);             CP_COMMIT();
    dn_fill(sb + DN_STAGE, A, Bp, rowBase, colBase, 64, tid); CP_COMMIT();

    int buf = 0;
    for (int t = 0; t < T; t++) {
        CP_WAIT1();
        __syncthreads();
        const uint32_t base  = sb + (uint32_t)buf * DN_STAGE;
        const uint32_t aBase = base + aOff;
        const uint32_t bBase = base + DN_ABYTES + bRowOff;

        const int tn = t + 2;
        if (tn < T) {
            int nb = buf + 2; if (nb >= 3) nb -= 3;
            dn_fill(sb + (uint32_t)nb * DN_STAGE, A, Bp,
                    rowBase, colBase, tn * 64, tid);
        }
        CP_COMMIT();

#pragma unroll
        for (int ks = 0; ks < 4; ks++) {
            uint32_t a[2][4], b[4][4];
            const uint32_t csw = (uint32_t)(((ks * 2 + hi) ^ (int)a_r7) << 4);
            ldsm4(a[0], aBase + csw);
            ldsm4(a[1], aBase + (16u << 7) + csw);
            const uint32_t bk = bBase + (uint32_t)ks * 4096;
#pragma unroll
            for (int p = 0; p < 4; p++) ldsm4t(b[p], bk + ncSw[p]);
#pragma unroll
            for (int mt = 0; mt < 2; mt++)
#pragma unroll
                for (int nt = 0; nt < 8; nt++)
                    mma16816(acc[mt][nt], a[mt], &b[nt >> 1][(nt & 1) * 2]);
        }
        buf++; if (buf == 3) buf = 0;
    }

    // ---- epilogue: out += wv * acc (atomic; exactly 2 adds/element, det.) ----
    const float wv = w[batch * 2 + ph];
#pragma unroll
    for (int mt = 0; mt < 2; mt++) {
        const int r0 = rowBase + wm + mt * 16 + lr;
#pragma unroll
        for (int nt = 0; nt < 8; nt++) {
            const int c = colBase + wn + nt * 8 + lc * 2;
            const size_t i0 = (size_t)r0 * D_MODEL + c;
            const size_t i1 = i0 + (size_t)8 * D_MODEL;
            red_add_f32(out + i0,     wv * acc[mt][nt][0]);
            red_add_f32(out + i0 + 1, wv * acc[mt][nt][1]);
            red_add_f32(out + i1,     wv * acc[mt][nt][2]);
            red_add_f32(out + i1 + 1, wv * acc[mt][nt][3]);
        }
    }
}

// ---------------- merged conversion kernel (also zeroes out) --------------------
__global__ __launch_bounds__(256)
void cvt_all(const float* __restrict__ X,
             const float* __restrict__ Wi0, const float* __restrict__ Wi1,
             const float* __restrict__ Wo,  const float* __restrict__ sWi0,
             const float* __restrict__ sWi1,const float* __restrict__ sWo,
             __half* __restrict__ Xh, __half* __restrict__ Wa,
             __half* __restrict__ Wb, __half* __restrict__ Wc,
             float* __restrict__ out)
{
    const size_t nX = (size_t)M_TOT * D_MODEL;
    const size_t nW = 6 * WSLOT;
    const size_t nE = 5 * WSLOT;
    size_t i = ((size_t)blockIdx.x * 256 + threadIdx.x) * 8;
    const float* src;
    __half* dst;
    if (i < nX) {
        src = X + i; dst = Xh + i;
        // zero the output accumulator (same index range)
        float4 z = make_float4(0.f, 0.f, 0.f, 0.f);
        *(float4*)(out + i)     = z;
        *(float4*)(out + i + 4) = z;
    } else {
        size_t j = i - nX;
        int wsel = (int)(j / nW);
        size_t k = j - (size_t)wsel * nW;
        const float* e = (wsel == 0) ? Wi0 : (wsel == 1) ? Wi1 : Wo;
        const float* s = (wsel == 0) ? sWi0 : (wsel == 1) ? sWi1 : sWo;
        src = (k < nE) ? e + k : s + (k - nE);
        dst = ((wsel == 0) ? Wa : (wsel == 1) ? Wb : Wc) + k;
    }
    float4 v0 = *(const float4*)(src);
    float4 v1 = *(const float4*)(src + 4);
    __half2* o = (__half2*)dst;
    o[0] = __floats2half2_rn(v0.x, v0.y);
    o[1] = __floats2half2_rn(v0.z, v0.w);
    o[2] = __floats2half2_rn(v1.x, v1.y);
    o[3] = __floats2half2_rn(v1.z, v1.w);
}

// ---------------- row-0 GEMV (k-split 8, half2-vectorized) ----------------------
__global__ __launch_bounds__(256)
void row0_kernel(const __half* __restrict__ H, const __half* __restrict__ H2,
                 const __half* __restrict__ Wc, const int* __restrict__ lbl,
                 float* __restrict__ gp)
{
    const int b = blockIdx.y, z = blockIdx.z;          // z: k-chunk of 512
    const int j2 = blockIdx.x * 256 + threadIdx.x;     // 0..1023 (pair index)
    const int j = j2 * 2;                              // 0..2046
    const bool sh = j >= D_MODEL;
    const int col = j & (D_MODEL - 1);
    const __half* A = (sh ? H2 : H) + (size_t)b * SEQ * D_FF + z * 512;
    const __half* Wp = Wc + (size_t)(sh ? 5 : lbl[b]) * WSLOT +
                       (size_t)z * 512 * D_MODEL + col;
    float a0 = 0.f, a1 = 0.f;
#pragma unroll 8
    for (int k = 0; k < 512; k++) {
        float x = __half2float(A[k]);
        __half2 wv = *(const __half2*)(Wp + (size_t)k * D_MODEL);
        a0 = fmaf(x, __low2float(wv), a0);
        a1 = fmaf(x, __high2float(wv), a1);
    }
    float* o = gp + ((size_t)z * BATCH + b) * 2 * D_MODEL + j;
    o[0] = a0;
    o[1] = a1;
}

// ---------------- gate stage 1 (k-split 32, proven 14us) ------------------------
__global__ __launch_bounds__(256)
void gate1(const float* __restrict__ gp, const float* __restrict__ g0,
           float* __restrict__ hp)
{
    const int col = blockIdx.x * 256 + threadIdx.x;
    const int z = blockIdx.y;                          // k-chunk of 64
    __shared__ float xs[64][8];

#pragma unroll
    for (int u = 0; u < 2; u++) {
        int e = threadIdx.x + u * 256;                 // 0..511
        int k0 = e >> 3, b = e & 7;
        int k = z * 64 + k0;
        float s = 0.f;
#pragma unroll
        for (int p = 0; p < 8; p++)
            s += gp[((size_t)p * BATCH + b) * 2 * D_MODEL + k];
        xs[k0][b] = s;
    }
    __syncthreads();

    float acc[8];
#pragma unroll
    for (int b = 0; b < 8; b++) acc[b] = 0.f;
#pragma unroll 4
    for (int k0 = 0; k0 < 64; k0++) {
        float g = g0[(size_t)(z * 64 + k0) * D_MODEL + col];
#pragma unroll
        for (int b = 0; b < 8; b++) acc[b] = fmaf(xs[k0][b], g, acc[b]);
    }
#pragma unroll
    for (int b = 0; b < 8; b++)
        hp[((size_t)z * BATCH + b) * D_MODEL + col] = acc[b];
}

// ---------------- gate stage 2 (warp-shuffle finish) ----------------------------
__global__ __launch_bounds__(256)
void gate2(const float* __restrict__ hp, const float* __restrict__ g1,
           float* __restrict__ w)
{
    const int b = blockIdx.x;
    float l0 = 0.f, l1 = 0.f;
#pragma unroll
    for (int u = 0; u < 4; u++) {
        const int j = threadIdx.x + 256 * u;
        float h = 0.f;
#pragma unroll
        for (int z = 0; z < 32; z++)
            h += hp[((size_t)z * BATCH + b) * D_MODEL + j];
        h = fmaxf(h, 0.f);
        l0 = fmaf(h, g1[j * 2 + 0], l0);
        l1 = fmaf(h, g1[j * 2 + 1], l1);
    }
#pragma unroll
    for (int s = 16; s > 0; s >>= 1) {
        l0 += __shfl_xor_sync(0xFFFFFFFFu, l0, s);
        l1 += __shfl_xor_sync(0xFFFFFFFFu, l1, s);
    }
    __shared__ float red0[8], red1[8];
    const int warp = threadIdx.x >> 5, lane = threadIdx.x & 31;
    if (lane == 0) { red0[warp] = l0; red1[warp] = l1; }
    __syncthreads();
    if (threadIdx.x == 0) {
        float a = 0.f, c = 0.f;
#pragma unroll
        for (int i = 0; i < 8; i++) { a += red0[i]; c += red1[i]; }
        float m  = fmaxf(a, c);
        float e0 = expf(a - m), e1 = expf(c - m);
        float inv = 1.f / (e0 + e1);
        w[b * 2 + 0] = e0 * inv;
        w[b * 2 + 1] = e1 * inv;
    }
}

// ---------------- launch -------------------------------------------------------
extern "C" void kernel_launch(void* const* d_in, const int* in_sizes, int n_in,
                              void* d_out, int out_size)
{
    const float* X    = (const float*)d_in[0];
    const int*   lbl  = (const int*)  d_in[1];
    const float* Wi0  = (const float*)d_in[2];
    const float* Wi1  = (const float*)d_in[3];
    const float* Wo   = (const float*)d_in[4];
    const float* sWi0 = (const float*)d_in[5];
    const float* sWi1 = (const float*)d_in[6];
    const float* sWo  = (const float*)d_in[7];
    const float* G0   = (const float*)d_in[8];
    const float* G1   = (const float*)d_in[9];
    float* out = (float*)d_out;

    __half *Xh, *H, *H2, *Wa, *Wb, *Wc;
    float *gp, *hp, *W;
    cudaGetSymbolAddress((void**)&Xh, g_Xh);
    cudaGetSymbolAddress((void**)&H,  g_H);
    cudaGetSymbolAddress((void**)&H2, g_H2);
    cudaGetSymbolAddress((void**)&Wa, g_Wa);
    cudaGetSymbolAddress((void**)&Wb, g_Wb);
    cudaGetSymbolAddress((void**)&Wc, g_Wc);
    cudaGetSymbolAddress((void**)&gp, g_gp);
    cudaGetSymbolAddress((void**)&hp, g_hp);
    cudaGetSymbolAddress((void**)&W,  g_W);

    cudaFuncSetAttribute(up_fused, cudaFuncAttributeMaxDynamicSharedMemorySize, UP_SMEM);
    cudaFuncSetAttribute(dn_split, cudaFuncAttributeMaxDynamicSharedMemorySize, DN_SMEM);

    const size_t nX = (size_t)M_TOT * D_MODEL;
    const size_t total = nX + 3 * 6 * WSLOT;
    dim3 grid_up(D_FF / 64, M_TOT / 128, 2);
    dim3 grid_dn(D_MODEL / 128, M_TOT / 128, 2);   // phase in z: 2048 CTAs

    cvt_all<<<(unsigned)(total / 2048), 256>>>(X, Wi0, Wi1, Wo, sWi0, sWi1, sWo,
                                               Xh, Wa, Wb, Wc, out);
    up_fused<<<grid_up, 256, UP_SMEM>>>(Xh, Wa, Wb, H, H2, lbl);
    row0_kernel<<<dim3(4, BATCH, 8), 256>>>(H, H2, Wc, lbl, gp);
    gate1<<<dim3(4, 32), 256>>>(gp, G0, hp);
    gate2<<<BATCH, 256>>>(hp, G1, W);
    dn_split<<<grid_dn, 256, DN_SMEM>>>(H, H2, Wc, out, lbl, W);
}

// round 16
// speedup vs baseline: 1.0213x; 1.0213x over previous
#include <cuda_runtime.h>
#include <cuda_fp16.h>
#include <math.h>
#include <stdint.h>

#define D_MODEL 1024
#define D_FF    4096
#define BATCH   8
#define SEQ     2048
#define M_TOT   (BATCH * SEQ)   // 16384
#define WSLOT   ((size_t)D_MODEL * D_FF)

// ---------------- scratch (allocation-free: __device__ globals) ----------------
__device__ __half g_Xh [(size_t)M_TOT * D_MODEL];  // 32 MB
__device__ __half g_H  [(size_t)M_TOT * D_FF];     // 128 MB expert H
__device__ __half g_H2 [(size_t)M_TOT * D_FF];     // 128 MB shared H
__device__ __half g_Wa [6 * WSLOT];                // Wi0[0:5], sWi0[5]
__device__ __half g_Wb [6 * WSLOT];                // Wi1[0:5], sWi1[5]
__device__ __half g_Wc [6 * WSLOT];                // Wo [0:5], sWo [5]
__device__ float  g_gp [8 * BATCH * 2 * D_MODEL];  // row0 partials (k-split 8)
__device__ float  g_hp [32 * BATCH * D_MODEL];     // gate1 partials (k-split 32)
__device__ float  g_W  [BATCH * 2];                // gate weights

// ---------------- helpers ------------------------------------------------------
__device__ __forceinline__ uint32_t smem_u32(const void* p) {
    uint32_t a;
    asm("{ .reg .u64 t; cvta.to.shared.u64 t, %1; cvt.u32.u64 %0, t; }"
        : "=r"(a) : "l"(p));
    return a;
}
__device__ __forceinline__ float gelu_tanh(float x) {
    float x3 = x * x * x;
    return 0.5f * x * (1.f + tanhf(0.7978845608028654f * (x + 0.044715f * x3)));
}
__device__ __forceinline__ void cp_async16(uint32_t saddr, const void* gaddr) {
    asm volatile("cp.async.cg.shared.global [%0], [%1], 16;"
                 :: "r"(saddr), "l"(gaddr) : "memory");
}
#define CP_COMMIT() asm volatile("cp.async.commit_group;" ::: "memory")
#define CP_WAIT1()  asm volatile("cp.async.wait_group 1;" ::: "memory")
#define CP_WAIT0()  asm volatile("cp.async.wait_group 0;" ::: "memory")

__device__ __forceinline__ void ldsm4(uint32_t* r, uint32_t addr) {
    asm volatile("ldmatrix.sync.aligned.m8n8.x4.shared.b16 {%0,%1,%2,%3}, [%4];"
                 : "=r"(r[0]), "=r"(r[1]), "=r"(r[2]), "=r"(r[3]) : "r"(addr));
}
__device__ __forceinline__ void ldsm4t(uint32_t* r, uint32_t addr) {
    asm volatile("ldmatrix.sync.aligned.m8n8.x4.trans.shared.b16 {%0,%1,%2,%3}, [%4];"
                 : "=r"(r[0]), "=r"(r[1]), "=r"(r[2]), "=r"(r[3]) : "r"(addr));
}
__device__ __forceinline__ void mma16816(float* d, const uint32_t* a, const uint32_t* b) {
    asm volatile(
        "mma.sync.aligned.m16n8k16.row.col.f32.f16.f16.f32 "
        "{%0,%1,%2,%3}, {%4,%5,%6,%7}, {%8,%9}, {%0,%1,%2,%3};"
        : "+f"(d[0]), "+f"(d[1]), "+f"(d[2]), "+f"(d[3])
        : "r"(a[0]), "r"(a[1]), "r"(a[2]), "r"(a[3]), "r"(b[0]), "r"(b[1]));
}

// ================================================================================
// Fused dual up-projection (proven): H = half(gelu(X@B0) * (X@B1)).
// ================================================================================
#define UP_STAGE 32768
#define UP_SMEM  (3 * UP_STAGE)

__device__ __forceinline__ void up_fill(uint32_t st, const __half* __restrict__ A,
                                        const __half* __restrict__ B0,
                                        const __half* __restrict__ B1,
                                        int rowBase, int colBase, int k0, int tid)
{
#pragma unroll
    for (int i = 0; i < 4; i++) {
        int c = tid + i * 256;
        int row = c >> 3, kc = c & 7;
        uint32_t dst = st + (row << 7) + (((kc ^ row) & 7) << 4);
        cp_async16(dst, A + (size_t)(rowBase + row) * D_MODEL + k0 + (kc << 3));
    }
#pragma unroll
    for (int i = 0; i < 2; i++) {
        int c = tid + i * 256;
        int row = c >> 3, nc = c & 7;
        uint32_t dst = st + 16384 + (row << 7) + (((nc ^ row) & 7) << 4);
        cp_async16(dst, B0 + (size_t)(k0 + row) * D_FF + colBase + (nc << 3));
    }
#pragma unroll
    for (int i = 0; i < 2; i++) {
        int c = tid + i * 256;
        int row = c >> 3, nc = c & 7;
        uint32_t dst = st + 24576 + (row << 7) + (((nc ^ row) & 7) << 4);
        cp_async16(dst, B1 + (size_t)(k0 + row) * D_FF + colBase + (nc << 3));
    }
}

__global__ __launch_bounds__(256, 2)
void up_fused(const __half* __restrict__ A, const __half* __restrict__ Wa,
              const __half* __restrict__ Wb, __half* __restrict__ He,
              __half* __restrict__ Hs, const int* __restrict__ labels)
{
    extern __shared__ char smem[];
    const uint32_t sb = smem_u32(smem);
    const int tid = threadIdx.x, lane = tid & 31, warp = tid >> 5;
    const int rowBase = blockIdx.y * 128, colBase = blockIdx.x * 64;
    const int slot = blockIdx.z ? 5 : labels[rowBase / SEQ];
    __half* H = blockIdx.z ? Hs : He;
    const __half* B0 = Wa + (size_t)slot * WSLOT;
    const __half* B1 = Wb + (size_t)slot * WSLOT;

    const int wm = (warp >> 1) * 32, wn = (warp & 1) * 32;
    const int lr = lane >> 2, lc = lane & 3;
    const int hi = lane >> 4;

    float acc[2][2][4][4];
#pragma unroll
    for (int m = 0; m < 2; m++)
#pragma unroll
        for (int mt = 0; mt < 2; mt++)
#pragma unroll
            for (int nt = 0; nt < 4; nt++)
#pragma unroll
                for (int i = 0; i < 4; i++) acc[m][mt][nt][i] = 0.f;

    const int aRow = wm + (lane & 15);
    const uint32_t aOff = (uint32_t)aRow << 7;
    const uint32_t a_r7 = aRow & 7;
    const uint32_t bRowOff = (uint32_t)(lane & 15) << 7;
    const uint32_t b_r7 = lane & 7;
    uint32_t ncSw[2];
#pragma unroll
    for (int p = 0; p < 2; p++) {
        int nchunk = (wn >> 3) + p * 2 + hi;
        ncSw[p] = (uint32_t)((nchunk ^ b_r7) & 7) << 4;
    }

    const int T = D_MODEL / 64;
    up_fill(sb, A, B0, B1, rowBase, colBase, 0, tid);             CP_COMMIT();
    up_fill(sb + UP_STAGE, A, B0, B1, rowBase, colBase, 64, tid); CP_COMMIT();

    int buf = 0;
    for (int t = 0; t < T; t++) {
        CP_WAIT1();
        __syncthreads();
        const uint32_t base  = sb + (uint32_t)buf * UP_STAGE;
        const uint32_t aBase = base + aOff;

        const int tn = t + 2;
        if (tn < T) {
            int nb = buf + 2; if (nb >= 3) nb -= 3;
            up_fill(sb + (uint32_t)nb * UP_STAGE, A, B0, B1,
                    rowBase, colBase, tn * 64, tid);
        }
        CP_COMMIT();

#pragma unroll
        for (int ks = 0; ks < 4; ks++) {
            uint32_t a[2][4], b[2][2][4];
            const uint32_t csw = (uint32_t)(((ks * 2 + hi) ^ (int)a_r7) << 4);
            ldsm4(a[0], aBase + csw);
            ldsm4(a[1], aBase + (16u << 7) + csw);
            const uint32_t bk = base + 16384 + bRowOff + (uint32_t)ks * 2048;
#pragma unroll
            for (int m = 0; m < 2; m++)
#pragma unroll
                for (int p = 0; p < 2; p++)
                    ldsm4t(b[m][p], bk + (uint32_t)m * 8192 + ncSw[p]);
#pragma unroll
            for (int m = 0; m < 2; m++)
#pragma unroll
                for (int mt = 0; mt < 2; mt++)
#pragma unroll
                    for (int nt = 0; nt < 4; nt++)
                        mma16816(acc[m][mt][nt], a[mt],
                                 &b[m][nt >> 1][(nt & 1) * 2]);
        }
        buf++; if (buf == 3) buf = 0;
    }

#pragma unroll
    for (int mt = 0; mt < 2; mt++) {
        const int r0 = rowBase + wm + mt * 16 + lr;
#pragma unroll
        for (int nt = 0; nt < 4; nt++) {
            const int c = colBase + wn + nt * 8 + lc * 2;
            const size_t i0 = (size_t)r0 * D_FF + c;
            const size_t i1 = i0 + (size_t)8 * D_FF;
            float v0 = gelu_tanh(acc[0][mt][nt][0]) * acc[1][mt][nt][0];
            float v1 = gelu_tanh(acc[0][mt][nt][1]) * acc[1][mt][nt][1];
            float v2 = gelu_tanh(acc[0][mt][nt][2]) * acc[1][mt][nt][2];
            float v3 = gelu_tanh(acc[0][mt][nt][3]) * acc[1][mt][nt][3];
            *(__half2*)(H + i0) = __floats2half2_rn(v0, v1);
            *(__half2*)(H + i1) = __floats2half2_rn(v2, v3);
        }
    }
}

// ================================================================================
// Fused down GEMM (R12-proven): out = w0*(H@Wo[lbl]) + w1*(H2@sWo).
// ================================================================================
#define DN_ABYTES 16384
#define DN_STAGE  32768
#define DN_SMEM   (3 * DN_STAGE)

__device__ __forceinline__ void dn_fill(uint32_t st, const __half* __restrict__ A,
                                        const __half* __restrict__ Bp,
                                        int rowBase, int colBase, int k0, int tid)
{
#pragma unroll
    for (int i = 0; i < 4; i++) {
        int c = tid + i * 256;
        int row = c >> 3, kc = c & 7;
        uint32_t dst = st + (row << 7) + (((kc ^ row) & 7) << 4);
        cp_async16(dst, A + (size_t)(rowBase + row) * D_FF + k0 + (kc << 3));
    }
#pragma unroll
    for (int i = 0; i < 4; i++) {
        int c = tid + i * 256;
        int row = c >> 4, nc = c & 15;
        uint32_t dst = st + DN_ABYTES + (row << 8) +
                       ((((nc ^ row) & 7) | (nc & 8)) << 4);
        cp_async16(dst, Bp + (size_t)(k0 + row) * D_MODEL + colBase + (nc << 3));
    }
}

__global__ __launch_bounds__(256, 2)
void dn_fused(const __half* __restrict__ He, const __half* __restrict__ Hs,
              const __half* __restrict__ Wc, float* __restrict__ out,
              const int* __restrict__ labels, const float* __restrict__ w)
{
    extern __shared__ char smem[];
    const uint32_t sb = smem_u32(smem);
    const int tid = threadIdx.x, lane = tid & 31, warp = tid >> 5;
    const int rowBase = blockIdx.y * 128, colBase = blockIdx.x * 128;
    const int batch = rowBase / SEQ;

    const int wm = (warp >> 1) * 32, wn = (warp & 1) * 64;
    const int lr = lane >> 2, lc = lane & 3;
    const int hi = lane >> 4;

    float acc[2][8][4];
#pragma unroll
    for (int mt = 0; mt < 2; mt++)
#pragma unroll
        for (int nt = 0; nt < 8; nt++)
#pragma unroll
            for (int i = 0; i < 4; i++) acc[mt][nt][i] = 0.f;

    const int aRow = wm + (lane & 15);
    const uint32_t aOff = (uint32_t)aRow << 7;
    const uint32_t a_r7 = aRow & 7;
    const uint32_t bRowOff = (uint32_t)(lane & 15) << 8;
    const uint32_t b_r7 = lane & 7;
    uint32_t ncSw[4];
#pragma unroll
    for (int p = 0; p < 4; p++) {
        int nchunk = (wn >> 3) + p * 2 + hi;
        ncSw[p] = (uint32_t)((nchunk & 8) | ((nchunk ^ b_r7) & 7)) << 4;
    }

    const float w0 = w[batch * 2 + 0], w1 = w[batch * 2 + 1];
    const int T = D_FF / 64;

    for (int ph = 0; ph < 2; ph++) {
        const __half* A  = ph ? Hs : He;
        const __half* Bp = Wc + (size_t)(ph ? 5 : labels[batch]) * WSLOT;

        dn_fill(sb, A, Bp, rowBase, colBase, 0, tid);             CP_COMMIT();
        dn_fill(sb + DN_STAGE, A, Bp, rowBase, colBase, 64, tid); CP_COMMIT();

        int buf = 0;
        for (int t = 0; t < T; t++) {
            CP_WAIT1();
            __syncthreads();
            const uint32_t base  = sb + (uint32_t)buf * DN_STAGE;
            const uint32_t aBase = base + aOff;
            const uint32_t bBase = base + DN_ABYTES + bRowOff;

            const int tn = t + 2;
            if (tn < T) {
                int nb = buf + 2; if (nb >= 3) nb -= 3;
                dn_fill(sb + (uint32_t)nb * DN_STAGE, A, Bp,
                        rowBase, colBase, tn * 64, tid);
            }
            CP_COMMIT();

#pragma unroll
            for (int ks = 0; ks < 4; ks++) {
                uint32_t a[2][4], b[4][4];
                const uint32_t csw = (uint32_t)(((ks * 2 + hi) ^ (int)a_r7) << 4);
                ldsm4(a[0], aBase + csw);
                ldsm4(a[1], aBase + (16u << 7) + csw);
                const uint32_t bk = bBase + (uint32_t)ks * 4096;
#pragma unroll
                for (int p = 0; p < 4; p++) ldsm4t(b[p], bk + ncSw[p]);
#pragma unroll
                for (int mt = 0; mt < 2; mt++)
#pragma unroll
                    for (int nt = 0; nt < 8; nt++)
                        mma16816(acc[mt][nt], a[mt], &b[nt >> 1][(nt & 1) * 2]);
            }
            buf++; if (buf == 3) buf = 0;
        }

        CP_WAIT0();
        __syncthreads();

        if (ph == 0) {
            const float r = w0 / w1;   // softmax(2): w1 in (0,1), never 0
#pragma unroll
            for (int mt = 0; mt < 2; mt++)
#pragma unroll
                for (int nt = 0; nt < 8; nt++)
#pragma unroll
                    for (int i = 0; i < 4; i++) acc[mt][nt][i] *= r;
        }
    }

#pragma unroll
    for (int mt = 0; mt < 2; mt++) {
        const int r0 = rowBase + wm + mt * 16 + lr;
#pragma unroll
        for (int nt = 0; nt < 8; nt++) {
            const int c = colBase + wn + nt * 8 + lc * 2;
            const size_t i0 = (size_t)r0 * D_MODEL + c;
            const size_t i1 = i0 + (size_t)8 * D_MODEL;
            *(float2*)(out + i0) =
                make_float2(w1 * acc[mt][nt][0], w1 * acc[mt][nt][1]);
            *(float2*)(out + i1) =
                make_float2(w1 * acc[mt][nt][2], w1 * acc[mt][nt][3]);
        }
    }
}

// ---------------- single merged conversion kernel -------------------------------
__global__ __launch_bounds__(256)
void cvt_all(const float* __restrict__ X,
             const float* __restrict__ Wi0, const float* __restrict__ Wi1,
             const float* __restrict__ Wo,  const float* __restrict__ sWi0,
             const float* __restrict__ sWi1,const float* __restrict__ sWo,
             __half* __restrict__ Xh, __half* __restrict__ Wa,
             __half* __restrict__ Wb, __half* __restrict__ Wc)
{
    const size_t nX = (size_t)M_TOT * D_MODEL;
    const size_t nW = 6 * WSLOT;
    const size_t nE = 5 * WSLOT;
    size_t i = ((size_t)blockIdx.x * 256 + threadIdx.x) * 8;
    const float* src;
    __half* dst;
    if (i < nX) { src = X + i; dst = Xh + i; }
    else {
        size_t j = i - nX;
        int wsel = (int)(j / nW);
        size_t k = j - (size_t)wsel * nW;
        const float* e = (wsel == 0) ? Wi0 : (wsel == 1) ? Wi1 : Wo;
        const float* s = (wsel == 0) ? sWi0 : (wsel == 1) ? sWi1 : sWo;
        src = (k < nE) ? e + k : s + (k - nE);
        dst = ((wsel == 0) ? Wa : (wsel == 1) ? Wb : Wc) + k;
    }
    float4 v0 = *(const float4*)(src);
    float4 v1 = *(const float4*)(src + 4);
    __half2* o = (__half2*)dst;
    o[0] = __floats2half2_rn(v0.x, v0.y);
    o[1] = __floats2half2_rn(v0.z, v0.w);
    o[2] = __floats2half2_rn(v1.x, v1.y);
    o[3] = __floats2half2_rn(v1.z, v1.w);
}

// ---------------- row-0 GEMV (k-split 8, half2-vectorized) ----------------------
__global__ __launch_bounds__(256)
void row0_kernel(const __half* __restrict__ H, const __half* __restrict__ H2,
                 const __half* __restrict__ Wc, const int* __restrict__ lbl,
                 float* __restrict__ gp)
{
    const int b = blockIdx.y, z = blockIdx.z;          // z: k-chunk of 512
    const int j2 = blockIdx.x * 256 + threadIdx.x;     // 0..1023 (pair index)
    const int j = j2 * 2;                              // 0..2046
    const bool sh = j >= D_MODEL;
    const int col = j & (D_MODEL - 1);
    const __half* A = (sh ? H2 : H) + (size_t)b * SEQ * D_FF + z * 512;
    const __half* Wp = Wc + (size_t)(sh ? 5 : lbl[b]) * WSLOT +
                       (size_t)z * 512 * D_MODEL + col;
    float a0 = 0.f, a1 = 0.f;
#pragma unroll 8
    for (int k = 0; k < 512; k++) {
        float x = __half2float(A[k]);
        __half2 wv = *(const __half2*)(Wp + (size_t)k * D_MODEL);
        a0 = fmaf(x, __low2float(wv), a0);
        a1 = fmaf(x, __high2float(wv), a1);
    }
    float* o = gp + ((size_t)z * BATCH + b) * 2 * D_MODEL + j;
    o[0] = a0;
    o[1] = a1;
}

// ---------------- gate stage 1 (k-split 32, proven 14us) ------------------------
__global__ __launch_bounds__(256)
void gate1(const float* __restrict__ gp, const float* __restrict__ g0,
           float* __restrict__ hp)
{
    const int col = blockIdx.x * 256 + threadIdx.x;
    const int z = blockIdx.y;                          // k-chunk of 64
    __shared__ float xs[64][8];

#pragma unroll
    for (int u = 0; u < 2; u++) {
        int e = threadIdx.x + u * 256;                 // 0..511
        int k0 = e >> 3, b = e & 7;
        int k = z * 64 + k0;
        float s = 0.f;
#pragma unroll
        for (int p = 0; p < 8; p++)
            s += gp[((size_t)p * BATCH + b) * 2 * D_MODEL + k];
        xs[k0][b] = s;
    }
    __syncthreads();

    float acc[8];
#pragma unroll
    for (int b = 0; b < 8; b++) acc[b] = 0.f;
#pragma unroll 4
    for (int k0 = 0; k0 < 64; k0++) {
        float g = g0[(size_t)(z * 64 + k0) * D_MODEL + col];
#pragma unroll
        for (int b = 0; b < 8; b++) acc[b] = fmaf(xs[k0][b], g, acc[b]);
    }
#pragma unroll
    for (int b = 0; b < 8; b++)
        hp[((size_t)z * BATCH + b) * D_MODEL + col] = acc[b];
}

// ---------------- gate stage 2 (warp-shuffle finish) ----------------------------
__global__ __launch_bounds__(256)
void gate2(const float* __restrict__ hp, const float* __restrict__ g1,
           float* __restrict__ w)
{
    const int b = blockIdx.x;
    float l0 = 0.f, l1 = 0.f;
#pragma unroll
    for (int u = 0; u < 4; u++) {
        const int j = threadIdx.x + 256 * u;
        float h = 0.f;
#pragma unroll
        for (int z = 0; z < 32; z++)
            h += hp[((size_t)z * BATCH + b) * D_MODEL + j];
        h = fmaxf(h, 0.f);
        l0 = fmaf(h, g1[j * 2 + 0], l0);
        l1 = fmaf(h, g1[j * 2 + 1], l1);
    }
#pragma unroll
    for (int s = 16; s > 0; s >>= 1) {
        l0 += __shfl_xor_sync(0xFFFFFFFFu, l0, s);
        l1 += __shfl_xor_sync(0xFFFFFFFFu, l1, s);
    }
    __shared__ float red0[8], red1[8];
    const int warp = threadIdx.x >> 5, lane = threadIdx.x & 31;
    if (lane == 0) { red0[warp] = l0; red1[warp] = l1; }
    __syncthreads();
    if (threadIdx.x == 0) {
        float a = 0.f, c = 0.f;
#pragma unroll
        for (int i = 0; i < 8; i++) { a += red0[i]; c += red1[i]; }
        float m  = fmaxf(a, c);
        float e0 = expf(a - m), e1 = expf(c - m);
        float inv = 1.f / (e0 + e1);
        w[b * 2 + 0] = e0 * inv;
        w[b * 2 + 1] = e1 * inv;
    }
}

// ---------------- launch -------------------------------------------------------
extern "C" void kernel_launch(void* const* d_in, const int* in_sizes, int n_in,
                              void* d_out, int out_size)
{
    const float* X    = (const float*)d_in[0];
    const int*   lbl  = (const int*)  d_in[1];
    const float* Wi0  = (const float*)d_in[2];
    const float* Wi1  = (const float*)d_in[3];
    const float* Wo   = (const float*)d_in[4];
    const float* sWi0 = (const float*)d_in[5];
    const float* sWi1 = (const float*)d_in[6];
    const float* sWo  = (const float*)d_in[7];
    const float* G0   = (const float*)d_in[8];
    const float* G1   = (const float*)d_in[9];
    float* out = (float*)d_out;

    __half *Xh, *H, *H2, *Wa, *Wb, *Wc;
    float *gp, *hp, *W;
    cudaGetSymbolAddress((void**)&Xh, g_Xh);
    cudaGetSymbolAddress((void**)&H,  g_H);
    cudaGetSymbolAddress((void**)&H2, g_H2);
    cudaGetSymbolAddress((void**)&Wa, g_Wa);
    cudaGetSymbolAddress((void**)&Wb, g_Wb);
    cudaGetSymbolAddress((void**)&Wc, g_Wc);
    cudaGetSymbolAddress((void**)&gp, g_gp);
    cudaGetSymbolAddress((void**)&hp, g_hp);
    cudaGetSymbolAddress((void**)&W,  g_W);

    cudaFuncSetAttribute(up_fused, cudaFuncAttributeMaxDynamicSharedMemorySize, UP_SMEM);
    cudaFuncSetAttribute(dn_fused, cudaFuncAttributeMaxDynamicSharedMemorySize, DN_SMEM);

    const size_t nX = (size_t)M_TOT * D_MODEL;
    const size_t total = nX + 3 * 6 * WSLOT;
    dim3 grid_up(D_FF / 64, M_TOT / 128, 2);
    dim3 grid_dn(D_MODEL / 128, M_TOT / 128);

    cvt_all<<<(unsigned)(total / 2048), 256>>>(X, Wi0, Wi1, Wo, sWi0, sWi1, sWo,
                                               Xh, Wa, Wb, Wc);
    up_fused<<<grid_up, 256, UP_SMEM>>>(Xh, Wa, Wb, H, H2, lbl);
    row0_kernel<<<dim3(4, BATCH, 8), 256>>>(H, H2, Wc, lbl, gp);
    gate1<<<dim3(4, 32), 256>>>(gp, G0, hp);
    gate2<<<BATCH, 256>>>(hp, G1, W);
    dn_fused<<<grid_dn, 256, DN_SMEM>>>(H, H2, Wc, out, lbl, W);
}